// round 6
// baseline (speedup 1.0000x reference)
#include <cuda_runtime.h>
#include <cuda_bf16.h>
#include <cstdint>
#include <math.h>

// Problem constants
#define Bn   32
#define Sn   2048
#define En   512
#define Vn   32000
#define NGRP 16      // batch groups
#define CPG  8       // CTAs per group (column split of W_dec)
#define NCOL 64      // columns per CTA
#define NTHR 512
#define SQRT_E 22.627416997969522f
#define EPSLN 1e-6f

// padded z layout: 8 blocks of 64 floats, each padded to 68 (conflict-free 8-way h-split)
#define ZBLK 68
#define ZROW (8 * ZBLK)                      // 544 floats per batch row
#define ZIDX0(i) (((i) >> 6) * ZBLK + ((i) & 63))

// ---------- static device scratch ----------
__device__ float    g_u[2 * NGRP * 2 * En];      // double-buffered u exchange
__device__ float    g_sf[2 * NGRP * 32];         // moment partials: 8 CTAs x 4 floats per (buf,group)
__device__ unsigned g_ep[NGRP * 32];             // per-CTA epochs, one 128B line per group
__device__ float    g_logits[(size_t)Bn * Vn];   // 4.1 MB logits scratch

// ---------- sync / PTX helpers ----------
__device__ __forceinline__ unsigned ld_acquire_u32(const unsigned* p) {
    unsigned v;
    asm volatile("ld.acquire.gpu.global.u32 %0, [%1];" : "=r"(v) : "l"(p) : "memory");
    return v;
}
__device__ __forceinline__ void st_release_u32(unsigned* p, unsigned v) {
    asm volatile("st.release.gpu.global.u32 [%0], %1;" :: "l"(p), "r"(v) : "memory");
}
// packed f32x2 FMA (Blackwell FFMA2): d += a * b (two independent IEEE fp32 lanes)
__device__ __forceinline__ void fma2(unsigned long long& d, unsigned long long a, unsigned long long b) {
    asm("fma.rn.f32x2 %0, %1, %2, %0;" : "+l"(d) : "l"(a), "l"(b));
}
__device__ __forceinline__ unsigned long long add2(unsigned long long a, unsigned long long b) {
    unsigned long long r; asm("add.rn.f32x2 %0, %1, %2;" : "=l"(r) : "l"(a), "l"(b)); return r;
}
__device__ __forceinline__ float sum2(unsigned long long v) {
    float a, b; asm("mov.b64 {%0, %1}, %2;" : "=f"(a), "=f"(b) : "l"(v)); return a + b;
}

// ===================== Kernel 1: recurrent scan =====================
// grid = 128 CTAs (16 groups x 8), 512 threads. CTA (g,c) owns W_dec
// columns [64c, 64c+64): thread (j = tid>>3, h = tid&7) holds rows
// [64h, 64h+64) of column J packed as 32 x f32x2 in registers.
// Per step: matvec -> 3 h-shuffles (all lanes get full column sums) ->
// u + warp stats shuffles -> named bar (w0 syncs, others arrive & poll) ->
// w0 folds partials, publishes gp + releases epoch -> all warps poll the
// 8 epoch words -> load gp line + own u slice -> LN fused with next emb.
__global__ void __launch_bounds__(NTHR, 1)
rnn_scan_kernel(const int* __restrict__ seq,
                const float* __restrict__ emb,
                const float* __restrict__ Wdec,
                const float* __restrict__ bdec,
                const float* __restrict__ gamma,
                const float* __restrict__ beta,
                float* __restrict__ outz)
{
    __shared__ __align__(16) float zs[2 * 2 * ZROW];   // double-buffered 2-batch state
    __shared__ __align__(16) float gs[En], bs_[En], bd[En];
    __shared__ __align__(16) float part[64];           // 16 warps x 4 moment partials

    const int tid  = threadIdx.x;
    const int lane = tid & 31;
    const int wid  = tid >> 5;
    const int g    = blockIdx.x >> 3;
    const int c    = blockIdx.x & 7;

    // matvec roles
    const int j = tid >> 3;                 // local column 0..63
    const int h = tid & 7;                  // 8-way row split (64 rows each)
    const int J = c * NCOL + j;             // global column
    // LN / emb roles (each thread owns one float2 slot)
    const int be = tid >> 8;                // batch half
    const int j2 = (tid & 255) * 2;         // float2 base 0..510
    const int brow = 2 * g + be;            // global batch row

    // ---- init: W column slice into registers (row pairs packed for f32x2) ----
    unsigned long long Wp[32];
    {
        const float* Wb = Wdec + (size_t)(h * 64) * En + J;
        #pragma unroll
        for (int k = 0; k < 32; ++k) {
            float w0 = __ldg(Wb + (size_t)(2 * k) * En);
            float w1 = __ldg(Wb + (size_t)(2 * k + 1) * En);
            asm("mov.b64 %0, {%1, %2};" : "=l"(Wp[k]) : "f"(w0), "f"(w1));
        }
    }
    for (int n = tid; n < En; n += NTHR) { gs[n] = gamma[n]; bs_[n] = beta[n]; bd[n] = bdec[n]; }
    // z_0 = sqrt(E) * x_0 into buffer 0
    {
        int idx = __ldg(&seq[brow * Sn + 0]);
        float2 e0 = __ldg((const float2*)&emb[(size_t)idx * En + j2]);
        *(float2*)&zs[be * ZROW + ZIDX0(j2)] = make_float2(e0.x * SQRT_E, e0.y * SQRT_E);
    }
    __syncthreads();

    for (int t = 0; t < Sn; ++t) {
        const int buf = t & 1;
        const int zb  = buf * (2 * ZROW);
        const int zn_ = (buf ^ 1) * (2 * ZROW);
        float* gu = &g_u[((buf * NGRP + g) * 2) * En];   // [2][512]
        float* gp = &g_sf[(buf * NGRP + g) * 32];        // 32 floats

        // prefetch next embedding (hidden under matvec)
        float2 epre = make_float2(0.f, 0.f);
        if (t + 1 < Sn) {
            int idx = __ldg(&seq[brow * Sn + (t + 1)]);
            epre = __ldg((const float2*)&emb[(size_t)idx * En + j2]);
        }

        // ---- matvec: 64 rows x 1 col x 2 batches, packed f32x2 ----
        float u0, u1;
        {
            unsigned long long a0e = 0ull, a0o = 0ull, a1e = 0ull, a1o = 0ull;
            const ulonglong2* zp0 = (const ulonglong2*)&zs[zb + h * ZBLK];
            const ulonglong2* zp1 = (const ulonglong2*)&zs[zb + ZROW + h * ZBLK];
            #pragma unroll
            for (int kk = 0; kk < 16; ++kk) {
                ulonglong2 za = zp0[kk];
                ulonglong2 zx = zp1[kk];
                fma2(a0e, Wp[2 * kk + 0], za.x);
                fma2(a0o, Wp[2 * kk + 1], za.y);
                fma2(a1e, Wp[2 * kk + 0], zx.x);
                fma2(a1o, Wp[2 * kk + 1], zx.y);
            }
            float mv0 = sum2(add2(a0e, a0o));
            float mv1 = sum2(add2(a1e, a1o));
            // combine the 8 h-partials (lane bits 0-2); all lanes end with full sums
            mv0 += __shfl_xor_sync(~0u, mv0, 1);  mv1 += __shfl_xor_sync(~0u, mv1, 1);
            mv0 += __shfl_xor_sync(~0u, mv0, 2);  mv1 += __shfl_xor_sync(~0u, mv1, 2);
            mv0 += __shfl_xor_sync(~0u, mv0, 4);  mv1 += __shfl_xor_sync(~0u, mv1, 4);
            u0 = zs[zb + ZIDX0(J)] + mv0 + bd[J];
            u1 = zs[zb + ZROW + ZIDX0(J)] + mv1 + bd[J];
            if (h == 0) { gu[J] = u0; gu[En + J] = u1; }
        }

        // ---- warp stats over its 4 columns (values identical across h-lanes) ----
        {
            float p0 = u0, q0 = u0 * u0, p1 = u1, q1 = u1 * u1;
            // sum across the 4 column groups (lane bits 3,4)
            p0 += __shfl_xor_sync(~0u, p0, 8);   q0 += __shfl_xor_sync(~0u, q0, 8);
            p1 += __shfl_xor_sync(~0u, p1, 8);   q1 += __shfl_xor_sync(~0u, q1, 8);
            p0 += __shfl_xor_sync(~0u, p0, 16);  q0 += __shfl_xor_sync(~0u, q0, 16);
            p1 += __shfl_xor_sync(~0u, p1, 16);  q1 += __shfl_xor_sync(~0u, q1, 16);
            if (lane == 0) *(float4*)&part[wid * 4] = make_float4(p0, q0, p1, q1);
        }

        // ---- named barrier: warps 1-15 arrive and go poll; warp 0 syncs ----
        if (wid == 0) {
            asm volatile("bar.sync 1, 512;" ::: "memory");
            // fold 16 warp partials (64 floats): lane i takes part[i] + part[i+32]
            float v = part[lane] + part[lane + 32];
            v += __shfl_xor_sync(~0u, v, 4);
            v += __shfl_xor_sync(~0u, v, 8);
            v += __shfl_xor_sync(~0u, v, 16);   // lane l: total of quantity (l&3)
            float v1 = __shfl_sync(~0u, v, 1);
            float v2 = __shfl_sync(~0u, v, 2);
            float v3 = __shfl_sync(~0u, v, 3);
            if (lane == 0) {
                *(float4*)&gp[c * 4] = make_float4(v, v1, v2, v3);   // plain store
                st_release_u32(&g_ep[g * 32 + c], (unsigned)(t + 1)); // orders gu/gp
            }
        } else {
            asm volatile("bar.arrive 1, 512;" ::: "memory");
        }

        // ---- poll the 8 epoch words (one 32B sector) ----
        {
            const unsigned tgt = (unsigned)(t + 1);
            bool ok;
            do {
                unsigned e = (lane < 8) ? ld_acquire_u32(&g_ep[g * 32 + lane]) : tgt;
                ok = __all_sync(~0u, e >= tgt);
            } while (!ok);
        }

        // ---- consumer: gp line + own u float2, redundant per-warp mu/rv ----
        {
            float mom = __ldcg(&gp[lane]);             // 8 CTAs x 4 partials
            float2 uu = __ldcg((const float2*)&gu[be * En + j2]);
            mom += __shfl_xor_sync(~0u, mom, 4);
            mom += __shfl_xor_sync(~0u, mom, 8);
            mom += __shfl_xor_sync(~0u, mom, 16);      // lane l: total of quantity (l&3)
            float S1 = __shfl_sync(~0u, mom, 2 * be);
            float S2 = __shfl_sync(~0u, mom, 2 * be + 1);
            float mu = S1 * (1.f / En);
            float va = (S2 - (float)En * mu * mu) * (1.f / (En - 1));
            float rv = __fdividef(1.f, sqrtf(va) + EPSLN);

            float2 gg = *(float2*)&gs[j2];
            float2 bb = *(float2*)&bs_[j2];
            float2 zo;
            zo.x = fmaf(gg.x, (uu.x - mu) * rv, bb.x) + SQRT_E * epre.x;
            zo.y = fmaf(gg.y, (uu.y - mu) * rv, bb.y) + SQRT_E * epre.y;
            *(float2*)&zs[zn_ + be * ZROW + ZIDX0(j2)] = zo;
        }
        __syncthreads();   // zs[buf^1] complete before next matvec
    }

    // final z lives in buffer 0 (Sn even); CTA c==0 of each group writes
    if (c == 0) {
        *(float2*)&outz[brow * En + j2] = *(float2*)&zs[be * ZROW + ZIDX0(j2)];
    }
}

// ===================== Kernel 2: logits = z @ W_voc + b_voc =====================
__global__ void __launch_bounds__(128)
vocab_gemm_kernel(const float* __restrict__ z,
                  const float* __restrict__ Wvoc,
                  const float* __restrict__ bvoc)
{
    extern __shared__ float zsh[];   // 32*512 floats = 64 KB
    for (int n = threadIdx.x; n < (Bn * En) / 4; n += 128)
        ((float4*)zsh)[n] = ((const float4*)z)[n];
    __syncthreads();

    const int v = blockIdx.x * 128 + threadIdx.x;
    float bias = __ldg(&bvoc[v]);
    float acc[Bn];
    #pragma unroll
    for (int b = 0; b < Bn; ++b) acc[b] = bias;

    for (int i = 0; i < En; i += 4) {
        float w0 = __ldg(&Wvoc[(size_t)(i + 0) * Vn + v]);
        float w1 = __ldg(&Wvoc[(size_t)(i + 1) * Vn + v]);
        float w2 = __ldg(&Wvoc[(size_t)(i + 2) * Vn + v]);
        float w3 = __ldg(&Wvoc[(size_t)(i + 3) * Vn + v]);
        #pragma unroll
        for (int b = 0; b < Bn; ++b) {
            float4 zz = *(const float4*)&zsh[b * En + i];
            acc[b] = fmaf(zz.x, w0, fmaf(zz.y, w1, fmaf(zz.z, w2, fmaf(zz.w, w3, acc[b]))));
        }
    }
    #pragma unroll
    for (int b = 0; b < Bn; ++b)
        g_logits[(size_t)b * Vn + v] = acc[b];
}

// ===================== Kernel 3: log_softmax + epoch reset =====================
__global__ void __launch_bounds__(256)
logsoftmax_kernel(float* __restrict__ dout)
{
    __shared__ float sb[34];
    const int row = blockIdx.x;
    const int tid = threadIdx.x;
    if (row == 0 && tid < NGRP * CPG)
        g_ep[(tid >> 3) * 32 + (tid & 7)] = 0u;   // reset for next graph replay

    const float* L = &g_logits[(size_t)row * Vn];

    float m = -INFINITY;
    for (int v = tid; v < Vn; v += 256) m = fmaxf(m, __ldg(&L[v]));
    #pragma unroll
    for (int off = 16; off; off >>= 1) m = fmaxf(m, __shfl_xor_sync(~0u, m, off));
    if ((tid & 31) == 0) sb[tid >> 5] = m;
    __syncthreads();
    if (tid < 8) {
        float mm = sb[tid];
        #pragma unroll
        for (int off = 4; off; off >>= 1) mm = fmaxf(mm, __shfl_xor_sync(0xffu, mm, off));
        if (tid == 0) sb[32] = mm;
    }
    __syncthreads();
    const float M = sb[32];
    __syncthreads();

    float s = 0.f;
    for (int v = tid; v < Vn; v += 256) s += expf(__ldg(&L[v]) - M);
    #pragma unroll
    for (int off = 16; off; off >>= 1) s += __shfl_xor_sync(~0u, s, off);
    if ((tid & 31) == 0) sb[tid >> 5] = s;
    __syncthreads();
    if (tid < 8) {
        float ss = sb[tid];
        #pragma unroll
        for (int off = 4; off; off >>= 1) ss += __shfl_xor_sync(0xffu, ss, off);
        if (tid == 0) sb[33] = ss;
    }
    __syncthreads();
    const float lse = M + logf(sb[33]);

    float* Y = dout + Bn * En + (size_t)row * Vn;
    for (int v = tid; v < Vn; v += 256) Y[v] = __ldg(&L[v]) - lse;
}

// ===================== launch =====================
extern "C" void kernel_launch(void* const* d_in, const int* in_sizes, int n_in,
                              void* d_out, int out_size)
{
    // inputs: hidden_state, output_sequence, emb_out, W_dec, b_dec, gamma, beta, W_voc, b_voc
    const int*   seq   = (const int*)  d_in[1];
    const float* emb   = (const float*)d_in[2];
    const float* Wdec  = (const float*)d_in[3];
    const float* bdec  = (const float*)d_in[4];
    const float* gamma = (const float*)d_in[5];
    const float* beta  = (const float*)d_in[6];
    const float* Wvoc  = (const float*)d_in[7];
    const float* bvoc  = (const float*)d_in[8];
    float* out = (float*)d_out;

    const int smem2 = Bn * En * (int)sizeof(float);   // 64 KB
    cudaFuncSetAttribute(vocab_gemm_kernel, cudaFuncAttributeMaxDynamicSharedMemorySize, smem2);

    rnn_scan_kernel<<<NGRP * CPG, NTHR>>>(seq, emb, Wdec, bdec, gamma, beta, out);
    vocab_gemm_kernel<<<Vn / 128, 128, smem2>>>(out, Wvoc, bvoc);
    logsoftmax_kernel<<<Bn, 256>>>(out);
}

// round 7
// speedup vs baseline: 1.4973x; 1.4973x over previous
#include <cuda_runtime.h>
#include <cuda_bf16.h>
#include <cstdint>
#include <math.h>

// Problem constants
#define Bn   32
#define Sn   2048
#define En   512
#define Vn   32000
#define NGRP 16      // batch groups
#define CPG  8       // CTAs per group (column split of W_dec)
#define NCOL 64      // columns per CTA
#define NTHR 256
#define SQRT_E 22.627416997969522f
#define EPSLN 1e-6f

// padded z layout: 4 blocks of 128 floats, each padded to 132 (conflict-free 4-way h-split)
#define ZBLK 132
#define ZROW (4 * ZBLK)                        // 528 floats per batch row
#define ZIDX(b, i) ((b) * ZROW + ((i) >> 7) * ZBLK + ((i) & 127))

// ---------- static device scratch ----------
__device__ float    g_u[2 * NGRP * 2 * En];      // [buf][group][batch][512] u exchange
__device__ float    g_p[2 * NGRP * 2 * 16];      // [buf][group][batch][16] CTA stat pairs
__device__ unsigned g_ctr[NGRP * 2 * 32];        // per (group,batch) counters, 128B apart
__device__ float    g_logits[(size_t)Bn * Vn];   // 4.1 MB logits scratch

// ---------- sync / PTX helpers ----------
__device__ __forceinline__ unsigned ld_acquire_u32(const unsigned* p) {
    unsigned v;
    asm volatile("ld.acquire.gpu.global.u32 %0, [%1];" : "=r"(v) : "l"(p) : "memory");
    return v;
}
__device__ __forceinline__ void red_release_add(unsigned* p, unsigned v) {
    asm volatile("red.release.gpu.global.add.u32 [%0], %1;" :: "l"(p), "r"(v) : "memory");
}
// packed f32x2 FMA (Blackwell FFMA2): d += a * b (two independent IEEE fp32 lanes)
__device__ __forceinline__ void fma2(unsigned long long& d, unsigned long long a, unsigned long long b) {
    asm("fma.rn.f32x2 %0, %1, %2, %0;" : "+l"(d) : "l"(a), "l"(b));
}
__device__ __forceinline__ unsigned long long add2(unsigned long long a, unsigned long long b) {
    unsigned long long r; asm("add.rn.f32x2 %0, %1, %2;" : "=l"(r) : "l"(a), "l"(b)); return r;
}
__device__ __forceinline__ float sum2(unsigned long long v) {
    float a, b; asm("mov.b64 {%0, %1}, %2;" : "=f"(a), "=f"(b) : "l"(v)); return a + b;
}

// ===================== Kernel 1: recurrent scan (2-batch pipelined) =====================
// grid = 128 CTAs (16 groups x 8), 256 threads. CTA (g,c) owns W_dec
// columns [64c,64c+64): thread (j = tid>>2, h = tid&3) holds rows
// [128h,128h+128) of column J packed as 64 x f32x2 in registers.
// Per step: P1 matvec b0 -> publish | P2 matvec b1 -> publish |
// P3 poll b0 (mostly elapsed) -> LN z0 | P4 poll b1 -> LN z1.
__global__ void __launch_bounds__(NTHR, 1)
rnn_scan_kernel(const int* __restrict__ seq,
                const float* __restrict__ emb,
                const float* __restrict__ Wdec,
                const float* __restrict__ bdec,
                const float* __restrict__ gamma,
                const float* __restrict__ beta,
                float* __restrict__ outz)
{
    __shared__ __align__(16) float zs[2 * ZROW];    // in-place 2-batch state
    __shared__ __align__(16) float gs[En], bs_[En], bd[En];
    __shared__ __align__(16) float2 part0[8];       // warp stat partials, phase-separate
    __shared__ __align__(16) float2 part1[8];

    const int tid  = threadIdx.x;
    const int lane = tid & 31;
    const int wid  = tid >> 5;
    const int g    = blockIdx.x >> 3;
    const int c    = blockIdx.x & 7;

    // matvec roles
    const int j = tid >> 2;                 // local column 0..63
    const int h = tid & 3;                  // 4-way row split (128 rows each)
    const int J = c * NCOL + j;             // global column
    // LN roles: thread owns one float2 slot (per batch)
    const int j2 = tid * 2;                 // 0..510
    const int brow0 = 2 * g, brow1 = 2 * g + 1;

    // ---- init: W column slice into registers (row pairs packed for f32x2) ----
    unsigned long long Wp[64];
    {
        const float* Wb = Wdec + (size_t)(h * 128) * En + J;
        #pragma unroll
        for (int k = 0; k < 64; ++k) {
            float w0 = __ldg(Wb + (size_t)(2 * k) * En);
            float w1 = __ldg(Wb + (size_t)(2 * k + 1) * En);
            asm("mov.b64 %0, {%1, %2};" : "=l"(Wp[k]) : "f"(w0), "f"(w1));
        }
    }
    for (int n = tid; n < En; n += NTHR) { gs[n] = gamma[n]; bs_[n] = beta[n]; bd[n] = bdec[n]; }
    // z_0 = sqrt(E) * x_0 for both batches
    {
        int i0 = __ldg(&seq[brow0 * Sn + 0]);
        int i1 = __ldg(&seq[brow1 * Sn + 0]);
        float2 e0 = __ldg((const float2*)&emb[(size_t)i0 * En + j2]);
        float2 e1 = __ldg((const float2*)&emb[(size_t)i1 * En + j2]);
        *(float2*)&zs[ZIDX(0, j2)] = make_float2(e0.x * SQRT_E, e0.y * SQRT_E);
        *(float2*)&zs[ZIDX(1, j2)] = make_float2(e1.x * SQRT_E, e1.y * SQRT_E);
    }
    __syncthreads();

    unsigned* ctr0 = &g_ctr[(2 * g + 0) * 32];
    unsigned* ctr1 = &g_ctr[(2 * g + 1) * 32];

    for (int t = 0; t < Sn; ++t) {
        const int buf = t & 1;
        float* gu0 = &g_u[(((size_t)buf * NGRP + g) * 2 + 0) * En];
        float* gu1 = &g_u[(((size_t)buf * NGRP + g) * 2 + 1) * En];
        float* gp0 = &g_p[(((size_t)buf * NGRP + g) * 2 + 0) * 16];
        float* gp1 = &g_p[(((size_t)buf * NGRP + g) * 2 + 1) * 16];
        const unsigned tgt = 8u * (unsigned)(t + 1);

        // prefetch next embeddings (hidden under matvecs)
        float2 e0 = make_float2(0.f, 0.f), e1 = make_float2(0.f, 0.f);
        if (t + 1 < Sn) {
            int i0 = __ldg(&seq[brow0 * Sn + (t + 1)]);
            int i1 = __ldg(&seq[brow1 * Sn + (t + 1)]);
            e0 = __ldg((const float2*)&emb[(size_t)i0 * En + j2]);
            e1 = __ldg((const float2*)&emb[(size_t)i1 * En + j2]);
        }

        // ================= P1: matvec + stage, batch 0 =================
        {
            unsigned long long ae = 0ull, ao = 0ull;
            const ulonglong2* zp = (const ulonglong2*)&zs[h * ZBLK];
            #pragma unroll
            for (int k = 0; k < 32; ++k) {
                ulonglong2 za = zp[k];
                fma2(ae, Wp[2 * k + 0], za.x);
                fma2(ao, Wp[2 * k + 1], za.y);
            }
            float mv = sum2(add2(ae, ao));
            mv += __shfl_xor_sync(~0u, mv, 1);
            mv += __shfl_xor_sync(~0u, mv, 2);
            float u = zs[ZIDX(0, J)] + mv + bd[J];
            if (h == 0) gu0[J] = u;                    // start L2 write early
            float s1 = u, s2 = u * u;
            s1 += __shfl_xor_sync(~0u, s1, 4);   s2 += __shfl_xor_sync(~0u, s2, 4);
            s1 += __shfl_xor_sync(~0u, s1, 8);   s2 += __shfl_xor_sync(~0u, s2, 8);
            s1 += __shfl_xor_sync(~0u, s1, 16);  s2 += __shfl_xor_sync(~0u, s2, 16);
            if (lane == 0) part0[wid] = make_float2(s1, s2);
        }
        __syncthreads();
        if (wid == 0) {   // fold 8 warp partials, publish, release (others run P2)
            float v = ((const float*)part0)[lane & 15];
            v += __shfl_xor_sync(~0u, v, 2);
            v += __shfl_xor_sync(~0u, v, 4);
            v += __shfl_xor_sync(~0u, v, 8);
            float v1 = __shfl_sync(~0u, v, 1);
            if (lane == 0) {
                *(float2*)&gp0[c * 2] = make_float2(v, v1);
                red_release_add(ctr0, 1u);
            }
        }

        // ================= P2: matvec + stage, batch 1 =================
        {
            unsigned long long ae = 0ull, ao = 0ull;
            const ulonglong2* zp = (const ulonglong2*)&zs[ZROW + h * ZBLK];
            #pragma unroll
            for (int k = 0; k < 32; ++k) {
                ulonglong2 za = zp[k];
                fma2(ae, Wp[2 * k + 0], za.x);
                fma2(ao, Wp[2 * k + 1], za.y);
            }
            float mv = sum2(add2(ae, ao));
            mv += __shfl_xor_sync(~0u, mv, 1);
            mv += __shfl_xor_sync(~0u, mv, 2);
            float u = zs[ZIDX(1, J)] + mv + bd[J];
            if (h == 0) gu1[J] = u;
            float s1 = u, s2 = u * u;
            s1 += __shfl_xor_sync(~0u, s1, 4);   s2 += __shfl_xor_sync(~0u, s2, 4);
            s1 += __shfl_xor_sync(~0u, s1, 8);   s2 += __shfl_xor_sync(~0u, s2, 8);
            s1 += __shfl_xor_sync(~0u, s1, 16);  s2 += __shfl_xor_sync(~0u, s2, 16);
            if (lane == 0) part1[wid] = make_float2(s1, s2);
        }
        __syncthreads();
        if (wid == 0) {
            float v = ((const float*)part1)[lane & 15];
            v += __shfl_xor_sync(~0u, v, 2);
            v += __shfl_xor_sync(~0u, v, 4);
            v += __shfl_xor_sync(~0u, v, 8);
            float v1 = __shfl_sync(~0u, v, 1);
            if (lane == 0) {
                *(float2*)&gp1[c * 2] = make_float2(v, v1);
                red_release_add(ctr1, 1u);
            }
        }

        // ================= P3: consume batch 0 (handshake mostly elapsed) =================
        {
            while (ld_acquire_u32(ctr0) < tgt) { }
            float  mom = __ldcg(&gp0[lane & 15]);               // 8 CTA stat pairs
            float2 uu  = __ldcg((const float2*)&gu0[j2]);       // own u slice
            mom += __shfl_xor_sync(~0u, mom, 2);
            mom += __shfl_xor_sync(~0u, mom, 4);
            mom += __shfl_xor_sync(~0u, mom, 8);
            float S1 = __shfl_sync(~0u, mom, 0);
            float S2 = __shfl_sync(~0u, mom, 1);
            float mu = S1 * (1.f / En);
            float va = (S2 - (float)En * mu * mu) * (1.f / (En - 1));
            float rv = __fdividef(1.f, sqrtf(va) + EPSLN);
            float2 gg = *(float2*)&gs[j2];
            float2 bb = *(float2*)&bs_[j2];
            float2 zo;
            zo.x = fmaf(gg.x, (uu.x - mu) * rv, bb.x) + SQRT_E * e0.x;
            zo.y = fmaf(gg.y, (uu.y - mu) * rv, bb.y) + SQRT_E * e0.y;
            *(float2*)&zs[ZIDX(0, j2)] = zo;
        }

        // ================= P4: consume batch 1 =================
        {
            while (ld_acquire_u32(ctr1) < tgt) { }
            float  mom = __ldcg(&gp1[lane & 15]);
            float2 uu  = __ldcg((const float2*)&gu1[j2]);
            mom += __shfl_xor_sync(~0u, mom, 2);
            mom += __shfl_xor_sync(~0u, mom, 4);
            mom += __shfl_xor_sync(~0u, mom, 8);
            float S1 = __shfl_sync(~0u, mom, 0);
            float S2 = __shfl_sync(~0u, mom, 1);
            float mu = S1 * (1.f / En);
            float va = (S2 - (float)En * mu * mu) * (1.f / (En - 1));
            float rv = __fdividef(1.f, sqrtf(va) + EPSLN);
            float2 gg = *(float2*)&gs[j2];
            float2 bb = *(float2*)&bs_[j2];
            float2 zo;
            zo.x = fmaf(gg.x, (uu.x - mu) * rv, bb.x) + SQRT_E * e1.x;
            zo.y = fmaf(gg.y, (uu.y - mu) * rv, bb.y) + SQRT_E * e1.y;
            *(float2*)&zs[ZIDX(1, j2)] = zo;
        }
        __syncthreads();   // z writes visible before next step's matvecs
    }

    // final z -> d_out (first B*E floats), CTA c==0 of each group writes
    if (c == 0) {
        *(float2*)&outz[brow0 * En + j2] = *(float2*)&zs[ZIDX(0, j2)];
        *(float2*)&outz[brow1 * En + j2] = *(float2*)&zs[ZIDX(1, j2)];
    }
}

// ===================== Kernel 2: logits = z @ W_voc + b_voc =====================
__global__ void __launch_bounds__(128)
vocab_gemm_kernel(const float* __restrict__ z,
                  const float* __restrict__ Wvoc,
                  const float* __restrict__ bvoc)
{
    extern __shared__ float zsh[];   // 32*512 floats = 64 KB
    for (int n = threadIdx.x; n < (Bn * En) / 4; n += 128)
        ((float4*)zsh)[n] = ((const float4*)z)[n];
    __syncthreads();

    const int v = blockIdx.x * 128 + threadIdx.x;
    float bias = __ldg(&bvoc[v]);
    float acc[Bn];
    #pragma unroll
    for (int b = 0; b < Bn; ++b) acc[b] = bias;

    for (int i = 0; i < En; i += 4) {
        float w0 = __ldg(&Wvoc[(size_t)(i + 0) * Vn + v]);
        float w1 = __ldg(&Wvoc[(size_t)(i + 1) * Vn + v]);
        float w2 = __ldg(&Wvoc[(size_t)(i + 2) * Vn + v]);
        float w3 = __ldg(&Wvoc[(size_t)(i + 3) * Vn + v]);
        #pragma unroll
        for (int b = 0; b < Bn; ++b) {
            float4 zz = *(const float4*)&zsh[b * En + i];
            acc[b] = fmaf(zz.x, w0, fmaf(zz.y, w1, fmaf(zz.z, w2, fmaf(zz.w, w3, acc[b]))));
        }
    }
    #pragma unroll
    for (int b = 0; b < Bn; ++b)
        g_logits[(size_t)b * Vn + v] = acc[b];
}

// ===================== Kernel 3: log_softmax + counter reset =====================
__global__ void __launch_bounds__(256)
logsoftmax_kernel(float* __restrict__ dout)
{
    __shared__ float sb[34];
    const int row = blockIdx.x;
    const int tid = threadIdx.x;
    if (row == 0 && tid < NGRP * 2) g_ctr[tid * 32] = 0u;   // reset for next replay

    const float* L = &g_logits[(size_t)row * Vn];

    float m = -INFINITY;
    for (int v = tid; v < Vn; v += 256) m = fmaxf(m, __ldg(&L[v]));
    #pragma unroll
    for (int off = 16; off; off >>= 1) m = fmaxf(m, __shfl_xor_sync(~0u, m, off));
    if ((tid & 31) == 0) sb[tid >> 5] = m;
    __syncthreads();
    if (tid < 8) {
        float mm = sb[tid];
        #pragma unroll
        for (int off = 4; off; off >>= 1) mm = fmaxf(mm, __shfl_xor_sync(0xffu, mm, off));
        if (tid == 0) sb[32] = mm;
    }
    __syncthreads();
    const float M = sb[32];
    __syncthreads();

    float s = 0.f;
    for (int v = tid; v < Vn; v += 256) s += expf(__ldg(&L[v]) - M);
    #pragma unroll
    for (int off = 16; off; off >>= 1) s += __shfl_xor_sync(~0u, s, off);
    if ((tid & 31) == 0) sb[tid >> 5] = s;
    __syncthreads();
    if (tid < 8) {
        float ss = sb[tid];
        #pragma unroll
        for (int off = 4; off; off >>= 1) ss += __shfl_xor_sync(0xffu, ss, off);
        if (tid == 0) sb[33] = ss;
    }
    __syncthreads();
    const float lse = M + logf(sb[33]);

    float* Y = dout + Bn * En + (size_t)row * Vn;
    for (int v = tid; v < Vn; v += 256) Y[v] = __ldg(&L[v]) - lse;
}

// ===================== launch =====================
extern "C" void kernel_launch(void* const* d_in, const int* in_sizes, int n_in,
                              void* d_out, int out_size)
{
    // inputs: hidden_state, output_sequence, emb_out, W_dec, b_dec, gamma, beta, W_voc, b_voc
    const int*   seq   = (const int*)  d_in[1];
    const float* emb   = (const float*)d_in[2];
    const float* Wdec  = (const float*)d_in[3];
    const float* bdec  = (const float*)d_in[4];
    const float* gamma = (const float*)d_in[5];
    const float* beta  = (const float*)d_in[6];
    const float* Wvoc  = (const float*)d_in[7];
    const float* bvoc  = (const float*)d_in[8];
    float* out = (float*)d_out;

    const int smem2 = Bn * En * (int)sizeof(float);   // 64 KB
    cudaFuncSetAttribute(vocab_gemm_kernel, cudaFuncAttributeMaxDynamicSharedMemorySize, smem2);

    rnn_scan_kernel<<<NGRP * CPG, NTHR>>>(seq, emb, Wdec, bdec, gamma, beta, out);
    vocab_gemm_kernel<<<Vn / 128, 128, smem2>>>(out, Wvoc, bvoc);
    logsoftmax_kernel<<<Bn, 256>>>(out);
}

// round 8
// speedup vs baseline: 1.8976x; 1.2673x over previous
#include <cuda_runtime.h>
#include <cuda_bf16.h>
#include <cstdint>
#include <math.h>

// Problem constants
#define Bn   32
#define Sn   2048
#define En   512
#define Vn   32000
#define NGRP 16      // batch groups
#define CPG  8       // CTAs per group (column split of W_dec)
#define NCOL 64      // columns per CTA
#define NTHR 256
#define SQRT_E 22.627416997969522f
#define EPSLN 1e-6f

// padded z layout: 4 blocks of 128 floats, each padded to 132 (conflict-free 4-way h-split)
#define ZBLK 132
#define ZROW (4 * ZBLK)                        // 528 floats per batch row
#define ZIDX(b, i) ((b) * ZROW + ((i) >> 7) * ZBLK + ((i) & 127))

// ---------- static device scratch ----------
__device__ float    g_u[2 * NGRP * 2 * En];      // [buf][group][batch][512] u exchange
__device__ float    g_p[2 * NGRP * 32];          // [buf][group][8 CTAs x 4 stats]
__device__ unsigned g_ctr[NGRP * 32];            // per-group counters, 128B apart
__device__ float    g_logits[(size_t)Bn * Vn];   // 4.1 MB logits scratch

// ---------- sync / PTX helpers ----------
__device__ __forceinline__ unsigned ld_acquire_u32(const unsigned* p) {
    unsigned v;
    asm volatile("ld.acquire.gpu.global.u32 %0, [%1];" : "=r"(v) : "l"(p) : "memory");
    return v;
}
__device__ __forceinline__ void red_release_add(unsigned* p, unsigned v) {
    asm volatile("red.release.gpu.global.add.u32 [%0], %1;" :: "l"(p), "r"(v) : "memory");
}
// packed f32x2 FMA (Blackwell FFMA2): d += a * b (two independent IEEE fp32 lanes)
__device__ __forceinline__ void fma2(unsigned long long& d, unsigned long long a, unsigned long long b) {
    asm("fma.rn.f32x2 %0, %1, %2, %0;" : "+l"(d) : "l"(a), "l"(b));
}
__device__ __forceinline__ unsigned long long add2(unsigned long long a, unsigned long long b) {
    unsigned long long r; asm("add.rn.f32x2 %0, %1, %2;" : "=l"(r) : "l"(a), "l"(b)); return r;
}
__device__ __forceinline__ float sum2(unsigned long long v) {
    float a, b; asm("mov.b64 {%0, %1}, %2;" : "=f"(a), "=f"(b) : "l"(v)); return a + b;
}

// ===================== Kernel 1: recurrent scan =====================
// grid = 128 CTAs (16 groups x 8), 256 threads. CTA (g,c) owns W_dec
// columns [64c,64c+64): thread (j = tid>>2, h = tid&3) holds rows
// [128h,128h+128) of column J packed as 64 x f32x2 in registers.
// Per step (2 barriers total):
//   loop-top barrier -> matvec both batches -> 2 u-fold shuffles ->
//   h0 lanes store u to L2 -> warp stat shuffles -> stage float4 ->
//   barrier -> warp0 folds+publishes+releases (others already polling) ->
//   all-warp converged poll -> load gp+u slice -> LN fused with next emb.
__global__ void __launch_bounds__(NTHR, 1)
rnn_scan_kernel(const int* __restrict__ seq,
                const float* __restrict__ emb,
                const float* __restrict__ Wdec,
                const float* __restrict__ bdec,
                const float* __restrict__ gamma,
                const float* __restrict__ beta,
                float* __restrict__ outz)
{
    __shared__ __align__(16) float zs[2 * ZROW];    // 2-batch state, padded
    __shared__ __align__(16) float gs[En], bs_[En], bd[En];
    __shared__ __align__(16) float4 part[8];        // per-warp stat partials

    const int tid  = threadIdx.x;
    const int lane = tid & 31;
    const int wid  = tid >> 5;
    const int g    = blockIdx.x >> 3;
    const int c    = blockIdx.x & 7;

    // matvec roles
    const int j = tid >> 2;                 // local column 0..63
    const int h = tid & 3;                  // 4-way row split (128 rows each)
    const int J = c * NCOL + j;             // global column
    // LN / emb roles: thread owns one float4 slot of one batch
    const int be = tid >> 7;                // batch half
    const int j4 = (tid << 2) & (En - 1);   // float4 base 0..508
    const int brow = 2 * g + be;            // global batch row

    // ---- init: W column slice into registers (row pairs packed for f32x2) ----
    unsigned long long Wp[64];
    {
        const float* Wb = Wdec + (size_t)(h * 128) * En + J;
        #pragma unroll
        for (int k = 0; k < 64; ++k) {
            float w0 = __ldg(Wb + (size_t)(2 * k) * En);
            float w1 = __ldg(Wb + (size_t)(2 * k + 1) * En);
            asm("mov.b64 %0, {%1, %2};" : "=l"(Wp[k]) : "f"(w0), "f"(w1));
        }
    }
    for (int n = tid; n < En; n += NTHR) { gs[n] = gamma[n]; bs_[n] = beta[n]; bd[n] = bdec[n]; }
    // z_0 = sqrt(E) * x_0
    {
        int idx = __ldg(&seq[brow * Sn + 0]);
        float4 e0 = __ldg((const float4*)&emb[(size_t)idx * En + j4]);
        *(float4*)&zs[ZIDX(be, j4)] =
            make_float4(e0.x * SQRT_E, e0.y * SQRT_E, e0.z * SQRT_E, e0.w * SQRT_E);
    }

    unsigned* ctr = &g_ctr[g * 32];

    for (int t = 0; t < Sn; ++t) {
        __syncthreads();   // B1: zs consistent for matvec

        const int buf = t & 1;
        float* gu = &g_u[((size_t)(buf * NGRP + g) * 2) * En];   // [2][512]
        float* gp = &g_p[(size_t)(buf * NGRP + g) * 32];         // 32 floats

        // prefetch next embedding (hidden under matvec)
        float4 epre = make_float4(0.f, 0.f, 0.f, 0.f);
        if (t + 1 < Sn) {
            int idx = __ldg(&seq[brow * Sn + (t + 1)]);
            epre = __ldg((const float4*)&emb[(size_t)idx * En + j4]);
        }

        // ---- matvec: 128 rows x 1 col x 2 batches, packed f32x2 ----
        float u0, u1;
        {
            unsigned long long a0e = 0ull, a0o = 0ull, a1e = 0ull, a1o = 0ull;
            const ulonglong2* zp0 = (const ulonglong2*)&zs[h * ZBLK];
            const ulonglong2* zp1 = (const ulonglong2*)&zs[ZROW + h * ZBLK];
            #pragma unroll
            for (int k = 0; k < 32; ++k) {
                ulonglong2 za = zp0[k];
                ulonglong2 zb = zp1[k];
                fma2(a0e, Wp[2 * k + 0], za.x);
                fma2(a0o, Wp[2 * k + 1], za.y);
                fma2(a1e, Wp[2 * k + 0], zb.x);
                fma2(a1o, Wp[2 * k + 1], zb.y);
            }
            float mv0 = sum2(add2(a0e, a0o));
            float mv1 = sum2(add2(a1e, a1o));
            // fold the 4 h-partials (lane bits 0-1); all lanes get full column sums
            mv0 += __shfl_xor_sync(~0u, mv0, 1);  mv1 += __shfl_xor_sync(~0u, mv1, 1);
            mv0 += __shfl_xor_sync(~0u, mv0, 2);  mv1 += __shfl_xor_sync(~0u, mv1, 2);
            u0 = zs[ZIDX(0, J)] + mv0 + bd[J];
            u1 = zs[ZIDX(1, J)] + mv1 + bd[J];
            if (h == 0) { gu[J] = u0; gu[En + J] = u1; }   // start L2 writes early
        }

        // ---- warp stats over its 8 columns (u duplicated across h-lanes) ----
        {
            float s10 = u0, s20 = u0 * u0, s11 = u1, s21 = u1 * u1;
            #pragma unroll
            for (int off = 4; off <= 16; off <<= 1) {
                s10 += __shfl_xor_sync(~0u, s10, off);
                s20 += __shfl_xor_sync(~0u, s20, off);
                s11 += __shfl_xor_sync(~0u, s11, off);
                s21 += __shfl_xor_sync(~0u, s21, off);
            }
            if (lane == 0) part[wid] = make_float4(s10, s20, s11, s21);
        }
        __syncthreads();   // B2: part[] + gu stores ordered before release

        // ---- warp0: fold 8 warp partials, publish, release (others go poll) ----
        if (wid == 0) {
            float v = ((const float*)part)[lane];   // w = lane>>2, q = lane&3
            v += __shfl_xor_sync(~0u, v, 4);
            v += __shfl_xor_sync(~0u, v, 8);
            v += __shfl_xor_sync(~0u, v, 16);       // lane l: total of quantity l&3
            float v0 = __shfl_sync(~0u, v, 0);
            float v1 = __shfl_sync(~0u, v, 1);
            float v2 = __shfl_sync(~0u, v, 2);
            float v3 = __shfl_sync(~0u, v, 3);
            if (lane == 0) {
                *(float4*)&gp[c * 4] = make_float4(v0, v1, v2, v3);
                red_release_add(ctr, 1u);
            }
        }

        // ---- all-warp converged poll on the group counter ----
        {
            const unsigned tgt = 8u * (unsigned)(t + 1);
            while (ld_acquire_u32(ctr) < tgt) { }
        }

        // ---- consume: gp line + own u float4, redundant per-warp stats ----
        {
            float mom = __ldcg(&gp[lane]);          // 8 CTAs x 4 partials
            float4 uu = __ldcg((const float4*)&gu[be * En + j4]);
            mom += __shfl_xor_sync(~0u, mom, 4);
            mom += __shfl_xor_sync(~0u, mom, 8);
            mom += __shfl_xor_sync(~0u, mom, 16);   // lane l: total of quantity l&3
            float S1 = __shfl_sync(~0u, mom, 2 * be);
            float S2 = __shfl_sync(~0u, mom, 2 * be + 1);
            float mu = S1 * (1.f / En);
            float va = (S2 - (float)En * mu * mu) * (1.f / (En - 1));
            float rv = __fdividef(1.f, sqrtf(va) + EPSLN);

            float4 gg = *(float4*)&gs[j4];
            float4 bb = *(float4*)&bs_[j4];
            float4 zn;
            zn.x = fmaf(gg.x, (uu.x - mu) * rv, bb.x) + SQRT_E * epre.x;
            zn.y = fmaf(gg.y, (uu.y - mu) * rv, bb.y) + SQRT_E * epre.y;
            zn.z = fmaf(gg.z, (uu.z - mu) * rv, bb.z) + SQRT_E * epre.z;
            zn.w = fmaf(gg.w, (uu.w - mu) * rv, bb.w) + SQRT_E * epre.w;
            *(float4*)&zs[ZIDX(be, j4)] = zn;
        }
        // loop-top barrier orders zs writes before the next matvec
    }

    // final z -> d_out (first B*E floats), CTA c==0 of each group writes
    if (c == 0) {
        *(float4*)&outz[brow * En + j4] = *(float4*)&zs[ZIDX(be, j4)];
    }
}

// ===================== Kernel 2: logits = z @ W_voc + b_voc =====================
__global__ void __launch_bounds__(128)
vocab_gemm_kernel(const float* __restrict__ z,
                  const float* __restrict__ Wvoc,
                  const float* __restrict__ bvoc)
{
    extern __shared__ float zsh[];   // 32*512 floats = 64 KB
    for (int n = threadIdx.x; n < (Bn * En) / 4; n += 128)
        ((float4*)zsh)[n] = ((const float4*)z)[n];
    __syncthreads();

    const int v = blockIdx.x * 128 + threadIdx.x;
    float bias = __ldg(&bvoc[v]);
    float acc[Bn];
    #pragma unroll
    for (int b = 0; b < Bn; ++b) acc[b] = bias;

    for (int i = 0; i < En; i += 4) {
        float w0 = __ldg(&Wvoc[(size_t)(i + 0) * Vn + v]);
        float w1 = __ldg(&Wvoc[(size_t)(i + 1) * Vn + v]);
        float w2 = __ldg(&Wvoc[(size_t)(i + 2) * Vn + v]);
        float w3 = __ldg(&Wvoc[(size_t)(i + 3) * Vn + v]);
        #pragma unroll
        for (int b = 0; b < Bn; ++b) {
            float4 zz = *(const float4*)&zsh[b * En + i];
            acc[b] = fmaf(zz.x, w0, fmaf(zz.y, w1, fmaf(zz.z, w2, fmaf(zz.w, w3, acc[b]))));
        }
    }
    #pragma unroll
    for (int b = 0; b < Bn; ++b)
        g_logits[(size_t)b * Vn + v] = acc[b];
}

// ===================== Kernel 3: log_softmax + counter reset =====================
__global__ void __launch_bounds__(256)
logsoftmax_kernel(float* __restrict__ dout)
{
    __shared__ float sb[34];
    const int row = blockIdx.x;
    const int tid = threadIdx.x;
    if (row == 0 && tid < NGRP) g_ctr[tid * 32] = 0u;   // reset for next replay

    const float* L = &g_logits[(size_t)row * Vn];

    float m = -INFINITY;
    for (int v = tid; v < Vn; v += 256) m = fmaxf(m, __ldg(&L[v]));
    #pragma unroll
    for (int off = 16; off; off >>= 1) m = fmaxf(m, __shfl_xor_sync(~0u, m, off));
    if ((tid & 31) == 0) sb[tid >> 5] = m;
    __syncthreads();
    if (tid < 8) {
        float mm = sb[tid];
        #pragma unroll
        for (int off = 4; off; off >>= 1) mm = fmaxf(mm, __shfl_xor_sync(0xffu, mm, off));
        if (tid == 0) sb[32] = mm;
    }
    __syncthreads();
    const float M = sb[32];
    __syncthreads();

    float s = 0.f;
    for (int v = tid; v < Vn; v += 256) s += expf(__ldg(&L[v]) - M);
    #pragma unroll
    for (int off = 16; off; off >>= 1) s += __shfl_xor_sync(~0u, s, off);
    if ((tid & 31) == 0) sb[tid >> 5] = s;
    __syncthreads();
    if (tid < 8) {
        float ss = sb[tid];
        #pragma unroll
        for (int off = 4; off; off >>= 1) ss += __shfl_xor_sync(0xffu, ss, off);
        if (tid == 0) sb[33] = ss;
    }
    __syncthreads();
    const float lse = M + logf(sb[33]);

    float* Y = dout + Bn * En + (size_t)row * Vn;
    for (int v = tid; v < Vn; v += 256) Y[v] = __ldg(&L[v]) - lse;
}

// ===================== launch =====================
extern "C" void kernel_launch(void* const* d_in, const int* in_sizes, int n_in,
                              void* d_out, int out_size)
{
    // inputs: hidden_state, output_sequence, emb_out, W_dec, b_dec, gamma, beta, W_voc, b_voc
    const int*   seq   = (const int*)  d_in[1];
    const float* emb   = (const float*)d_in[2];
    const float* Wdec  = (const float*)d_in[3];
    const float* bdec  = (const float*)d_in[4];
    const float* gamma = (const float*)d_in[5];
    const float* beta  = (const float*)d_in[6];
    const float* Wvoc  = (const float*)d_in[7];
    const float* bvoc  = (const float*)d_in[8];
    float* out = (float*)d_out;

    const int smem2 = Bn * En * (int)sizeof(float);   // 64 KB
    cudaFuncSetAttribute(vocab_gemm_kernel, cudaFuncAttributeMaxDynamicSharedMemorySize, smem2);

    rnn_scan_kernel<<<NGRP * CPG, NTHR>>>(seq, emb, Wdec, bdec, gamma, beta, out);
    vocab_gemm_kernel<<<Vn / 128, 128, smem2>>>(out, Wvoc, bvoc);
    logsoftmax_kernel<<<Bn, 256>>>(out);
}